// round 15
// baseline (speedup 1.0000x reference)
#include <cuda_runtime.h>
#include <cuda_fp16.h>
#include <cstdint>

// ---------------- problem constants ----------------
constexpr int T_  = 4096;
constexpr int D_  = 1024;
constexpr int H_  = 4096;
constexpr int E_  = 8;
constexpr int TOPK = 2;

constexpr int TM = 128;
constexpr int RP = 9216;
constexpr int NT = RP / TM;      // 72 row tiles

// mma GEMM tiling: CTA 128x256, 8 warps of 64x64, KC=64 double-buffered
constexpr int KC   = 64;           // K elems per chunk
constexpr int RSB  = 144;          // smem row stride bytes (128B data + 16B pad)
constexpr int PL_A = 128 * RSB;    // 18432 B
constexpr int PL_B = 256 * RSB;    // 36864 B
constexpr int STG_T = PL_A + PL_B; // 55296 B per stage
constexpr int SMEM_G = 2048 + 2 * STG_T;   // 112640 B

// ---------------- device-global scratch (256B-aligned: cp.async-safe) ----
__device__ __align__(256) int   g_top_i[2 * T_];
__device__ __align__(256) float g_top_w[2 * T_];
__device__ __align__(256) float g_probs[T_ * E_];
__device__ __align__(256) float g_probsum[E_];
__device__ __align__(256) int   g_cnt[E_];
__device__ __align__(256) int   g_cursor[E_];
__device__ __align__(256) int   g_aoff[E_ + 1];
__device__ __align__(256) int   g_tile_expert[NT];
__device__ __align__(256) int   g_assign_token[RP];
__device__ __align__(256) float g_assign_w[RP];
__device__ __align__(256) int   g_token_slot[2 * T_];

__device__ __align__(256) __half g_x16[T_ * D_];
__device__ __align__(256) __half g_w1[E_ * H_ * D_];  // W1^T: [E][H][D] K-major
__device__ __align__(256) __half g_w2[E_ * D_ * H_];  // W2^T: [E][D][H] K-major
__device__ __align__(256) __half g_hh[RP * H_];       // h in fp16
__device__ __align__(256) float g_y[(size_t)RP * D_];

// ---------------- PTX helpers (baseline PTX only) ----------------
__device__ __forceinline__ uint32_t smem_u32(const void* p) {
    return (uint32_t)__cvta_generic_to_shared(p);
}
__device__ __forceinline__ void cpa16(uint32_t s, const void* g) {
    asm volatile("cp.async.cg.shared.global [%0], [%1], 16;\n" :: "r"(s), "l"(g));
}
__device__ __forceinline__ void cpa_commit() {
    asm volatile("cp.async.commit_group;\n" ::: "memory");
}
__device__ __forceinline__ void mma_f16(float* d, const uint32_t* a, const uint32_t* b) {
    asm volatile(
        "mma.sync.aligned.m16n8k16.row.col.f32.f16.f16.f32 "
        "{%0,%1,%2,%3}, {%4,%5,%6,%7}, {%8,%9}, {%0,%1,%2,%3};"
        : "+f"(d[0]), "+f"(d[1]), "+f"(d[2]), "+f"(d[3])
        : "r"(a[0]), "r"(a[1]), "r"(a[2]), "r"(a[3]), "r"(b[0]), "r"(b[1]));
}

// ---------------- reset ----------------
__global__ void k_reset() {
    int i = blockIdx.x * blockDim.x + threadIdx.x;
    if (i < RP) { g_assign_token[i] = -1; g_assign_w[i] = 0.f; }
    if (i < E_) g_cnt[i] = 0;
}

// ---------------- router ----------------
__global__ void k_router(const float* __restrict__ x, const float* __restrict__ Wg) {
    int t = blockIdx.x;
    int lane = threadIdx.x & 31, w = threadIdx.x >> 5;
    const float* xt = x + (size_t)t * D_;
    const float* wg = Wg + (size_t)w * D_;
    float s = 0.f;
    #pragma unroll 8
    for (int j = lane; j < D_; j += 32) s += xt[j] * wg[j];
    #pragma unroll
    for (int o = 16; o; o >>= 1) s += __shfl_xor_sync(0xffffffffu, s, o);
    __shared__ float sl[E_];
    if (lane == 0) sl[w] = s;
    __syncthreads();
    if (threadIdx.x == 0) {
        float mx = sl[0];
        #pragma unroll
        for (int e = 1; e < E_; e++) mx = fmaxf(mx, sl[e]);
        float p[E_], sum = 0.f;
        #pragma unroll
        for (int e = 0; e < E_; e++) { p[e] = __expf(sl[e] - mx); sum += p[e]; }
        float inv = 1.f / sum;
        #pragma unroll
        for (int e = 0; e < E_; e++) { p[e] *= inv; g_probs[t * E_ + e] = p[e]; }
        int i0 = 0;
        #pragma unroll
        for (int e = 1; e < E_; e++) if (p[e] > p[i0]) i0 = e;
        int i1 = -1;
        #pragma unroll
        for (int e = 0; e < E_; e++) {
            if (e == i0) continue;
            if (i1 < 0 || p[e] > p[i1]) i1 = e;
        }
        float v0 = p[i0], v1 = p[i1], s2 = v0 + v1;
        g_top_i[2 * t] = i0;  g_top_i[2 * t + 1] = i1;
        g_top_w[2 * t] = v0 / s2;  g_top_w[2 * t + 1] = v1 / s2;
        atomicAdd(&g_cnt[i0], 1);
        atomicAdd(&g_cnt[i1], 1);
    }
}

__global__ void k_probs_reduce() {
    int e = blockIdx.x, tid = threadIdx.x;
    float s = 0.f;
    for (int t = tid; t < T_; t += 256) s += g_probs[t * E_ + e];
    __shared__ float red[256];
    red[tid] = s; __syncthreads();
    for (int o = 128; o; o >>= 1) { if (tid < o) red[tid] += red[tid + o]; __syncthreads(); }
    if (tid == 0) g_probsum[e] = red[0];
}

__global__ void k_plan() {
    if (threadIdx.x == 0) {
        int off = 0;
        for (int e = 0; e < E_; e++) {
            g_aoff[e] = off;
            int c = g_cnt[e];
            int tiles = (c + TM - 1) / TM;
            int bt = off / TM;
            for (int tt = 0; tt < tiles; tt++) g_tile_expert[bt + tt] = e;
            off += tiles * TM;
            g_cursor[e] = 0;
        }
        g_aoff[E_] = off;
        for (int m = off / TM; m < NT; m++) g_tile_expert[m] = -1;
    }
}

__global__ void k_scatter() {
    int t = blockIdx.x * blockDim.x + threadIdx.x;
    if (t >= T_) return;
    #pragma unroll
    for (int k = 0; k < TOPK; k++) {
        int e = g_top_i[2 * t + k];
        int pos = atomicAdd(&g_cursor[e], 1);
        int slot = g_aoff[e] + pos;
        g_assign_token[slot] = t;
        g_assign_w[slot] = g_top_w[2 * t + k];
        g_token_slot[2 * t + k] = slot;
    }
}

// ---------------- prep: fp32 -> fp16 ----------------
__global__ void k_cvt_x(const float* __restrict__ x) {
    int i = blockIdx.x * 256 + threadIdx.x;
    if (i < T_ * D_) g_x16[i] = __float2half(x[i]);
}

// transpose: W [E][R][Cc] -> global plane [E][Cc][R] fp16.
// Destination __device__ symbol selected INSIDE device code (host-shadow trap).
template<bool W1SEL>
__global__ void k_tr(const float* __restrict__ W) {
    constexpr int R  = W1SEL ? D_ : H_;   // contraction dim
    constexpr int Cc = W1SEL ? H_ : D_;   // output-major dim
    __half* Oh = W1SEL ? g_w1 : g_w2;
    __shared__ float t[32][33];
    int ez = blockIdx.z;
    const float* We = W + (size_t)ez * R * Cc;
    int c0 = blockIdx.x * 32, r0 = blockIdx.y * 32;
    int tx = threadIdx.x, ty = threadIdx.y;
    #pragma unroll
    for (int i = ty; i < 32; i += 8)
        t[i][tx] = We[(size_t)(r0 + i) * Cc + c0 + tx];
    __syncthreads();
    __half* OhE = Oh + (size_t)ez * R * Cc;
    #pragma unroll
    for (int i = ty; i < 32; i += 8)
        OhE[(size_t)(c0 + i) * R + r0 + tx] = __float2half(t[tx][i]);
}

// ---------------- grouped GEMM via mma.sync (pure fp16) ----------------
// CTA 128x256, KC=64 double-buffered cp.async, 8 warps of 64x64.
// Direct per-thread LDS.32 fragment loads (mma m16n8k16 documented coords).
template<bool G1>
__global__ __launch_bounds__(256) void k_gemm_mma(const float* __restrict__ bias_all) {
    int mt = blockIdx.y, nb = blockIdx.x;
    int e = g_tile_expert[mt];
    if (e < 0) return;
    extern __shared__ char smem[];
    float* s_bias = (float*)smem;                // 256 floats
    int*   s_tok  = (int*)(smem + 1024);         // 128 ints
    char*  sdata  = smem + 2048;
    uint32_t sb32 = smem_u32(smem) + 2048;
    constexpr int KD  = G1 ? D_ : H_;
    constexpr int NBW = G1 ? H_ : D_;
    constexpr int C   = KD / KC;
    int tid = threadIdx.x, lane = tid & 31, wid = tid >> 5;
    int row0 = mt * TM;

    s_bias[tid] = bias_all[(size_t)e * NBW + nb * 256 + tid];
    if (G1 && tid < 128) { int tk = g_assign_token[row0 + tid]; s_tok[tid] = tk < 0 ? 0 : tk; }
    __syncthreads();

    const __half* A = G1 ? g_x16 : g_hh;
    const __half* B = G1 ? g_w1  : g_w2;
    size_t bbase = (size_t)e * (size_t)H_ * D_ + (size_t)(nb * 256) * KD;

    auto load_chunk = [&](int c, int s) {
        uint32_t st = sb32 + s * STG_T;
        int k0 = c * KC;
        #pragma unroll
        for (int q = tid; q < 1024; q += 256) {          // A: 128 rows x 128B
            int r = q >> 3, cc = q & 7;
            size_t go = (G1 ? (size_t)s_tok[r] * D_ : (size_t)(row0 + r) * H_) + k0 + cc * 8;
            cpa16(st + (uint32_t)(r * RSB + cc * 16), A + go);
        }
        #pragma unroll
        for (int q = tid; q < 2048; q += 256) {          // B: 256 rows x 128B
            int r = q >> 3, cc = q & 7;
            size_t go = bbase + (size_t)r * KD + k0 + cc * 8;
            cpa16(st + PL_A + (uint32_t)(r * RSB + cc * 16), B + go);
        }
        cpa_commit();
    };

    int wm = (wid & 1) * 64, wn = (wid >> 1) * 64;       // warp 64x64
    int g = lane >> 2, tig = lane & 3;
    uint32_t aF = (uint32_t)((wm + g) * RSB + tig * 4);
    uint32_t bF = (uint32_t)((wn + g) * RSB + tig * 4);

    float acc[4][8][4] = {};
    load_chunk(0, 0);
    for (int c = 0; c < C; ++c) {
        int s = c & 1;
        if (c + 1 < C) {
            load_chunk(c + 1, s ^ 1);
            asm volatile("cp.async.wait_group 1;\n" ::: "memory");
        } else {
            asm volatile("cp.async.wait_group 0;\n" ::: "memory");
        }
        __syncthreads();
        char* pA = sdata + s * STG_T;
        char* pB = pA + PL_A;
        #pragma unroll
        for (int ks = 0; ks < 4; ks++) {
            uint32_t ko = ks * 32;
            uint32_t am[16], bx[16];
            #pragma unroll
            for (int m = 0; m < 4; m++) {
                uint32_t base = aF + m * 16 * RSB + ko;
                am[4 * m + 0] = *(const uint32_t*)(pA + base);
                am[4 * m + 1] = *(const uint32_t*)(pA + base + 8 * RSB);
                am[4 * m + 2] = *(const uint32_t*)(pA + base + 16);
                am[4 * m + 3] = *(const uint32_t*)(pA + base + 8 * RSB + 16);
            }
            #pragma unroll
            for (int n = 0; n < 8; n++) {
                uint32_t base = bF + n * 8 * RSB + ko;
                bx[2 * n + 0] = *(const uint32_t*)(pB + base);
                bx[2 * n + 1] = *(const uint32_t*)(pB + base + 16);
            }
            #pragma unroll
            for (int m = 0; m < 4; m++)
                #pragma unroll
                for (int n = 0; n < 8; n++)
                    mma_f16(acc[m][n], am + 4 * m, bx + 2 * n);
        }
        __syncthreads();
    }

    // ---- epilogue ----
    int rbase = row0 + wm + g;
    int cloc0 = wn + tig * 2;
    #pragma unroll
    for (int m = 0; m < 4; m++) {
        #pragma unroll
        for (int n = 0; n < 8; n++) {
            int cl = cloc0 + n * 8;
            int gc = nb * 256 + cl;
            float b0 = s_bias[cl], b1 = s_bias[cl + 1];
            #pragma unroll
            for (int hrow = 0; hrow < 2; hrow++) {
                int gr = rbase + m * 16 + hrow * 8;
                float v0 = acc[m][n][2 * hrow + 0] + b0;
                float v1 = acc[m][n][2 * hrow + 1] + b1;
                if (G1) {
                    float s0 = v0 * __fdividef(1.f, 1.f + __expf(-v0));
                    float s1 = v1 * __fdividef(1.f, 1.f + __expf(-v1));
                    __half2 hp; hp.x = __float2half(s0); hp.y = __float2half(s1);
                    *(__half2*)(g_hh + (size_t)gr * H_ + gc) = hp;
                } else {
                    size_t o = (size_t)gr * D_ + gc;
                    float2 fv; fv.x = v0; fv.y = v1;
                    *(float2*)(g_y + o) = fv;
                }
            }
        }
    }
}

// ---------------- combine + aux ----------------
__global__ void k_combine(float* __restrict__ out) {
    int idx = blockIdx.x * 256 + threadIdx.x;
    if (idx >= T_ * D_ / 4) return;
    int t = idx / (D_ / 4);
    int v = idx % (D_ / 4);
    int s0 = g_token_slot[2 * t], s1 = g_token_slot[2 * t + 1];
    float w0 = g_assign_w[s0], w1 = g_assign_w[s1];
    float4 y0 = *(const float4*)(g_y + (size_t)s0 * D_ + v * 4);
    float4 y1 = *(const float4*)(g_y + (size_t)s1 * D_ + v * 4);
    float4 o;
    o.x = w0 * y0.x + w1 * y1.x;
    o.y = w0 * y0.y + w1 * y1.y;
    o.z = w0 * y0.z + w1 * y1.z;
    o.w = w0 * y0.w + w1 * y1.w;
    *(float4*)(out + (size_t)t * D_ + v * 4) = o;
}

__global__ void k_aux(float* __restrict__ out, int out_size) {
    if (threadIdx.x == 0 && out_size > T_ * D_) {
        float a = 0.f;
        #pragma unroll
        for (int e = 0; e < E_; e++)
            a += ((float)g_cnt[e] / (float)T_) * (g_probsum[e] / (float)T_);
        out[(size_t)T_ * D_] = (float)E_ * a;
    }
}

// ---------------- launch ----------------
extern "C" void kernel_launch(void* const* d_in, const int* in_sizes, int n_in,
                              void* d_out, int out_size) {
    const float* x  = (const float*)d_in[0];
    const float* Wg = (const float*)d_in[1];
    const float* W1 = (const float*)d_in[2];
    const float* b1 = (const float*)d_in[3];
    const float* W2 = (const float*)d_in[4];
    const float* b2 = (const float*)d_in[5];
    float* out = (float*)d_out;
    (void)in_sizes; (void)n_in;

    cudaFuncSetAttribute(k_gemm_mma<true>,
                         cudaFuncAttributeMaxDynamicSharedMemorySize, SMEM_G);
    cudaFuncSetAttribute(k_gemm_mma<false>,
                         cudaFuncAttributeMaxDynamicSharedMemorySize, SMEM_G);

    k_reset<<<(RP + 255) / 256, 256>>>();
    k_router<<<T_, 256>>>(x, Wg);
    k_probs_reduce<<<E_, 256>>>();
    k_plan<<<1, 32>>>();
    k_scatter<<<(T_ + 255) / 256, 256>>>();

    // prep: fp32 -> fp16, weights transposed K-major
    k_cvt_x<<<(T_ * D_ + 255) / 256, 256>>>(x);
    k_tr<true ><<<dim3(H_ / 32, D_ / 32, E_), dim3(32, 8)>>>(W1);
    k_tr<false><<<dim3(D_ / 32, H_ / 32, E_), dim3(32, 8)>>>(W2);

    k_gemm_mma<true ><<<dim3(H_ / 256, NT), 256, SMEM_G>>>(b1);
    k_gemm_mma<false><<<dim3(D_ / 256, NT), 256, SMEM_G>>>(b2);

    k_combine<<<(T_ * D_ / 4 + 255) / 256, 256>>>(out);
    k_aux<<<1, 32>>>(out, out_size);
}

// round 16
// speedup vs baseline: 1.3153x; 1.3153x over previous
#include <cuda_runtime.h>
#include <cuda_fp16.h>
#include <cstdint>

// ---------------- problem constants ----------------
constexpr int T_  = 4096;
constexpr int D_  = 1024;
constexpr int H_  = 4096;
constexpr int E_  = 8;
constexpr int TOPK = 2;

constexpr int TM = 128;
constexpr int RP = 9216;
constexpr int NT = RP / TM;      // 72 row tiles

// mma GEMM tiling (R14 config: CTA 128x128, 8 warps 32x64, KC=32, 2-stage)
constexpr int KC  = 32;          // K elems per chunk
constexpr int RSB = 80;          // smem row stride bytes (64B data + 16B pad)
constexpr int PL  = 128 * RSB;   // 10240 B per plane (128 rows)
constexpr int SMEM_G = 1024 + 2 * 2 * PL;   // A,B x 2 stages = 41984 B

// ---------------- device-global scratch (256B-aligned: cp.async-safe) ----
__device__ __align__(256) int   g_top_i[2 * T_];
__device__ __align__(256) float g_top_w[2 * T_];
__device__ __align__(256) float g_probs[T_ * E_];
__device__ __align__(256) float g_probsum[E_];
__device__ __align__(256) int   g_cnt[E_];
__device__ __align__(256) int   g_cursor[E_];
__device__ __align__(256) int   g_aoff[E_ + 1];
__device__ __align__(256) int   g_tile_expert[NT];
__device__ __align__(256) int   g_assign_token[RP];
__device__ __align__(256) float g_assign_w[RP];
__device__ __align__(256) int   g_token_slot[2 * T_];

__device__ __align__(256) __half g_x16[T_ * D_];
__device__ __align__(256) __half g_w1[E_ * H_ * D_];  // W1^T: [E][H][D] K-major
__device__ __align__(256) __half g_w2[E_ * D_ * H_];  // W2^T: [E][D][H] K-major
__device__ __align__(256) __half g_hh[RP * H_];       // h in fp16
__device__ __align__(256) float g_y[(size_t)RP * D_];

// ---------------- PTX helpers (baseline PTX only) ----------------
__device__ __forceinline__ uint32_t smem_u32(const void* p) {
    return (uint32_t)__cvta_generic_to_shared(p);
}
__device__ __forceinline__ void cpa16(uint32_t s, const void* g) {
    asm volatile("cp.async.cg.shared.global [%0], [%1], 16;\n" :: "r"(s), "l"(g));
}
__device__ __forceinline__ void cpa_commit() {
    asm volatile("cp.async.commit_group;\n" ::: "memory");
}
__device__ __forceinline__ void ldm_x4(uint32_t* r, uint32_t a) {
    asm volatile("ldmatrix.sync.aligned.m8n8.x4.shared.b16 {%0,%1,%2,%3}, [%4];"
                 : "=r"(r[0]), "=r"(r[1]), "=r"(r[2]), "=r"(r[3]) : "r"(a));
}
__device__ __forceinline__ void mma_f16(float* d, const uint32_t* a, const uint32_t* b) {
    asm volatile(
        "mma.sync.aligned.m16n8k16.row.col.f32.f16.f16.f32 "
        "{%0,%1,%2,%3}, {%4,%5,%6,%7}, {%8,%9}, {%0,%1,%2,%3};"
        : "+f"(d[0]), "+f"(d[1]), "+f"(d[2]), "+f"(d[3])
        : "r"(a[0]), "r"(a[1]), "r"(a[2]), "r"(a[3]), "r"(b[0]), "r"(b[1]));
}

// ---------------- reset ----------------
__global__ void k_reset() {
    int i = blockIdx.x * blockDim.x + threadIdx.x;
    if (i < RP) { g_assign_token[i] = -1; g_assign_w[i] = 0.f; }
    if (i < E_) g_cnt[i] = 0;
}

// ---------------- router ----------------
__global__ void k_router(const float* __restrict__ x, const float* __restrict__ Wg) {
    int t = blockIdx.x;
    int lane = threadIdx.x & 31, w = threadIdx.x >> 5;
    const float* xt = x + (size_t)t * D_;
    const float* wg = Wg + (size_t)w * D_;
    float s = 0.f;
    #pragma unroll 8
    for (int j = lane; j < D_; j += 32) s += xt[j] * wg[j];
    #pragma unroll
    for (int o = 16; o; o >>= 1) s += __shfl_xor_sync(0xffffffffu, s, o);
    __shared__ float sl[E_];
    if (lane == 0) sl[w] = s;
    __syncthreads();
    if (threadIdx.x == 0) {
        float mx = sl[0];
        #pragma unroll
        for (int e = 1; e < E_; e++) mx = fmaxf(mx, sl[e]);
        float p[E_], sum = 0.f;
        #pragma unroll
        for (int e = 0; e < E_; e++) { p[e] = __expf(sl[e] - mx); sum += p[e]; }
        float inv = 1.f / sum;
        #pragma unroll
        for (int e = 0; e < E_; e++) { p[e] *= inv; g_probs[t * E_ + e] = p[e]; }
        int i0 = 0;
        #pragma unroll
        for (int e = 1; e < E_; e++) if (p[e] > p[i0]) i0 = e;
        int i1 = -1;
        #pragma unroll
        for (int e = 0; e < E_; e++) {
            if (e == i0) continue;
            if (i1 < 0 || p[e] > p[i1]) i1 = e;
        }
        float v0 = p[i0], v1 = p[i1], s2 = v0 + v1;
        g_top_i[2 * t] = i0;  g_top_i[2 * t + 1] = i1;
        g_top_w[2 * t] = v0 / s2;  g_top_w[2 * t + 1] = v1 / s2;
        atomicAdd(&g_cnt[i0], 1);
        atomicAdd(&g_cnt[i1], 1);
    }
}

__global__ void k_probs_reduce() {
    int e = blockIdx.x, tid = threadIdx.x;
    float s = 0.f;
    for (int t = tid; t < T_; t += 256) s += g_probs[t * E_ + e];
    __shared__ float red[256];
    red[tid] = s; __syncthreads();
    for (int o = 128; o; o >>= 1) { if (tid < o) red[tid] += red[tid + o]; __syncthreads(); }
    if (tid == 0) g_probsum[e] = red[0];
}

__global__ void k_plan() {
    if (threadIdx.x == 0) {
        int off = 0;
        for (int e = 0; e < E_; e++) {
            g_aoff[e] = off;
            int c = g_cnt[e];
            int tiles = (c + TM - 1) / TM;
            int bt = off / TM;
            for (int tt = 0; tt < tiles; tt++) g_tile_expert[bt + tt] = e;
            off += tiles * TM;
            g_cursor[e] = 0;
        }
        g_aoff[E_] = off;
        for (int m = off / TM; m < NT; m++) g_tile_expert[m] = -1;
    }
}

__global__ void k_scatter() {
    int t = blockIdx.x * blockDim.x + threadIdx.x;
    if (t >= T_) return;
    #pragma unroll
    for (int k = 0; k < TOPK; k++) {
        int e = g_top_i[2 * t + k];
        int pos = atomicAdd(&g_cursor[e], 1);
        int slot = g_aoff[e] + pos;
        g_assign_token[slot] = t;
        g_assign_w[slot] = g_top_w[2 * t + k];
        g_token_slot[2 * t + k] = slot;
    }
}

// ---------------- prep: fp32 -> fp16 ----------------
__global__ void k_cvt_x(const float* __restrict__ x) {
    int i = blockIdx.x * 256 + threadIdx.x;
    if (i < T_ * D_) g_x16[i] = __float2half(x[i]);
}

// transpose: W [E][R][Cc] -> global plane [E][Cc][R] fp16.
// Destination __device__ symbol selected INSIDE device code (host-shadow trap).
template<bool W1SEL>
__global__ void k_tr(const float* __restrict__ W) {
    constexpr int R  = W1SEL ? D_ : H_;   // contraction dim
    constexpr int Cc = W1SEL ? H_ : D_;   // output-major dim
    __half* Oh = W1SEL ? g_w1 : g_w2;
    __shared__ float t[32][33];
    int ez = blockIdx.z;
    const float* We = W + (size_t)ez * R * Cc;
    int c0 = blockIdx.x * 32, r0 = blockIdx.y * 32;
    int tx = threadIdx.x, ty = threadIdx.y;
    #pragma unroll
    for (int i = ty; i < 32; i += 8)
        t[i][tx] = We[(size_t)(r0 + i) * Cc + c0 + tx];
    __syncthreads();
    __half* OhE = Oh + (size_t)ez * R * Cc;
    #pragma unroll
    for (int i = ty; i < 32; i += 8)
        OhE[(size_t)(c0 + i) * R + r0 + tx] = __float2half(t[tx][i]);
}

// ---------------- grouped GEMM via mma.sync (pure fp16, ldmatrix frags) ----
// CTA 128x128, KC=32 double-buffered cp.async, 8 warps of 32x64.
// Fragments via ldmatrix.x4: A tile m16k16 = {a0,a1,a2,a3}; B pair n16k16
// (two n8 blocks) = {b0(2j),b1(2j),b0(2j+1),b1(2j+1)}. Smem [row][k] RSB=80
// keeps the 8 row-starts per phase on distinct 16B banks (conflict-free).
template<bool G1>
__global__ __launch_bounds__(256) void k_gemm_mma(const float* __restrict__ bias_all) {
    int mt = blockIdx.y, nb = blockIdx.x;
    int e = g_tile_expert[mt];
    if (e < 0) return;
    extern __shared__ char smem[];
    float* s_bias = (float*)smem;
    int*   s_tok  = (int*)(smem + 512);
    uint32_t sb32 = smem_u32(smem) + 1024;
    constexpr int KD  = G1 ? D_ : H_;
    constexpr int NBW = G1 ? H_ : D_;
    constexpr int C   = KD / KC;
    constexpr int STG_T = 2 * PL;              // A + B per stage
    int tid = threadIdx.x, lane = tid & 31, wid = tid >> 5;
    int row0 = mt * TM;

    if (tid < 128) s_bias[tid] = bias_all[(size_t)e * NBW + nb * 128 + tid];
    if (G1 && tid < 128) { int tk = g_assign_token[row0 + tid]; s_tok[tid] = tk < 0 ? 0 : tk; }
    __syncthreads();

    const __half* A = G1 ? g_x16 : g_hh;
    const __half* B = G1 ? g_w1  : g_w2;
    size_t bbase = (size_t)e * (size_t)H_ * D_ + (size_t)(nb * 128) * KD;

    auto load_chunk = [&](int c, int s) {
        uint32_t st = sb32 + s * STG_T;
        int k0 = c * KC;
        #pragma unroll
        for (int q = tid; q < 512; q += 256) {           // A: 128 rows x 64B
            int r = q >> 2, cc = q & 3;
            size_t go = (G1 ? (size_t)s_tok[r] * D_ : (size_t)(row0 + r) * H_) + k0 + cc * 8;
            cpa16(st + (uint32_t)(r * RSB + cc * 16), A + go);
        }
        #pragma unroll
        for (int q = tid; q < 512; q += 256) {           // B: 128 rows x 64B
            int r = q >> 2, cc = q & 3;
            size_t go = bbase + (size_t)r * KD + k0 + cc * 8;
            cpa16(st + PL + (uint32_t)(r * RSB + cc * 16), B + go);
        }
        cpa_commit();
    };

    int wm = (wid & 3) * 32, wn = (wid >> 2) * 64;
    int g = lane >> 2, tig = lane & 3;
    // ldmatrix per-lane row addresses (byte offsets within plane):
    // A x4 groups: {rows+0..7 kLo, rows+8..15 kLo, rows+0..7 kHi, rows+8..15 kHi}
    //   -> regs {a0,a1,a2,a3}
    uint32_t aLM = (uint32_t)((wm + (lane & 7) + ((lane >> 3) & 1) * 8) * RSB
                              + (lane >> 4) * 16);
    // B x4 groups: {rows+0..7 kLo, rows+0..7 kHi, rows+8..15 kLo, rows+8..15 kHi}
    //   -> regs {b0(2j),b1(2j),b0(2j+1),b1(2j+1)}
    uint32_t bLM = (uint32_t)((wn + (lane & 7) + ((lane >> 4) << 3)) * RSB
                              + ((lane >> 3) & 1) * 16);

    float acc[2][8][4] = {};
    load_chunk(0, 0);
    for (int c = 0; c < C; ++c) {
        int s = c & 1;
        if (c + 1 < C) {
            load_chunk(c + 1, s ^ 1);
            asm volatile("cp.async.wait_group 1;\n" ::: "memory");
        } else {
            asm volatile("cp.async.wait_group 0;\n" ::: "memory");
        }
        __syncthreads();
        uint32_t pA = sb32 + s * STG_T;
        uint32_t pB = pA + PL;
        #pragma unroll
        for (int ks = 0; ks < 2; ks++) {
            uint32_t ko = ks * 32;
            uint32_t am[8], bx[16];
            ldm_x4(am,     pA + aLM + ko);               // m-tile 0
            ldm_x4(am + 4, pA + aLM + 16 * RSB + ko);    // m-tile 1
            #pragma unroll
            for (int j = 0; j < 4; j++)                  // n-block pairs
                ldm_x4(bx + 4 * j, pB + bLM + j * 16 * RSB + ko);
            #pragma unroll
            for (int m = 0; m < 2; m++)
                #pragma unroll
                for (int n = 0; n < 8; n++)
                    mma_f16(acc[m][n], am + 4 * m, bx + 4 * (n >> 1) + 2 * (n & 1));
        }
        __syncthreads();
    }

    // ---- epilogue ----
    int rbase = row0 + wm + g;
    int cloc0 = wn + tig * 2;
    #pragma unroll
    for (int m = 0; m < 2; m++) {
        #pragma unroll
        for (int n = 0; n < 8; n++) {
            int cl = cloc0 + n * 8;
            int gc = nb * 128 + cl;
            float b0 = s_bias[cl], b1 = s_bias[cl + 1];
            #pragma unroll
            for (int hrow = 0; hrow < 2; hrow++) {
                int gr = rbase + m * 16 + hrow * 8;
                float v0 = acc[m][n][2 * hrow + 0] + b0;
                float v1 = acc[m][n][2 * hrow + 1] + b1;
                if (G1) {
                    float s0 = v0 * __fdividef(1.f, 1.f + __expf(-v0));
                    float s1 = v1 * __fdividef(1.f, 1.f + __expf(-v1));
                    __half2 hp; hp.x = __float2half(s0); hp.y = __float2half(s1);
                    *(__half2*)(g_hh + (size_t)gr * H_ + gc) = hp;
                } else {
                    size_t o = (size_t)gr * D_ + gc;
                    float2 fv; fv.x = v0; fv.y = v1;
                    *(float2*)(g_y + o) = fv;
                }
            }
        }
    }
}

// ---------------- combine + aux ----------------
__global__ void k_combine(float* __restrict__ out) {
    int idx = blockIdx.x * 256 + threadIdx.x;
    if (idx >= T_ * D_ / 4) return;
    int t = idx / (D_ / 4);
    int v = idx % (D_ / 4);
    int s0 = g_token_slot[2 * t], s1 = g_token_slot[2 * t + 1];
    float w0 = g_assign_w[s0], w1 = g_assign_w[s1];
    float4 y0 = *(const float4*)(g_y + (size_t)s0 * D_ + v * 4);
    float4 y1 = *(const float4*)(g_y + (size_t)s1 * D_ + v * 4);
    float4 o;
    o.x = w0 * y0.x + w1 * y1.x;
    o.y = w0 * y0.y + w1 * y1.y;
    o.z = w0 * y0.z + w1 * y1.z;
    o.w = w0 * y0.w + w1 * y1.w;
    *(float4*)(out + (size_t)t * D_ + v * 4) = o;
}

__global__ void k_aux(float* __restrict__ out, int out_size) {
    if (threadIdx.x == 0 && out_size > T_ * D_) {
        float a = 0.f;
        #pragma unroll
        for (int e = 0; e < E_; e++)
            a += ((float)g_cnt[e] / (float)T_) * (g_probsum[e] / (float)T_);
        out[(size_t)T_ * D_] = (float)E_ * a;
    }
}

// ---------------- launch ----------------
extern "C" void kernel_launch(void* const* d_in, const int* in_sizes, int n_in,
                              void* d_out, int out_size) {
    const float* x  = (const float*)d_in[0];
    const float* Wg = (const float*)d_in[1];
    const float* W1 = (const float*)d_in[2];
    const float* b1 = (const float*)d_in[3];
    const float* W2 = (const float*)d_in[4];
    const float* b2 = (const float*)d_in[5];
    float* out = (float*)d_out;
    (void)in_sizes; (void)n_in;

    cudaFuncSetAttribute(k_gemm_mma<true>,
                         cudaFuncAttributeMaxDynamicSharedMemorySize, SMEM_G);
    cudaFuncSetAttribute(k_gemm_mma<false>,
                         cudaFuncAttributeMaxDynamicSharedMemorySize, SMEM_G);

    k_reset<<<(RP + 255) / 256, 256>>>();
    k_router<<<T_, 256>>>(x, Wg);
    k_probs_reduce<<<E_, 256>>>();
    k_plan<<<1, 32>>>();
    k_scatter<<<(T_ + 255) / 256, 256>>>();

    // prep: fp32 -> fp16, weights transposed K-major
    k_cvt_x<<<(T_ * D_ + 255) / 256, 256>>>(x);
    k_tr<true ><<<dim3(H_ / 32, D_ / 32, E_), dim3(32, 8)>>>(W1);
    k_tr<false><<<dim3(D_ / 32, H_ / 32, E_), dim3(32, 8)>>>(W2);

    k_gemm_mma<true ><<<dim3(H_ / 128, NT), 256, SMEM_G>>>(b1);
    k_gemm_mma<false><<<dim3(D_ / 128, NT), 256, SMEM_G>>>(b2);

    k_combine<<<(T_ * D_ / 4 + 255) / 256, 256>>>(out);
    k_aux<<<1, 32>>>(out, out_size);
}

// round 17
// speedup vs baseline: 1.3716x; 1.0428x over previous
#include <cuda_runtime.h>
#include <cuda_fp16.h>
#include <cstdint>

// ---------------- problem constants ----------------
constexpr int T_  = 4096;
constexpr int D_  = 1024;
constexpr int H_  = 4096;
constexpr int E_  = 8;
constexpr int TOPK = 2;

constexpr int TM = 128;
constexpr int RP = 9216;
constexpr int NT = RP / TM;      // 72 row tiles

// mma GEMM tiling: CTA 128x128, 8 warps 32x64, KC=32, 2-stage
constexpr int KC    = 32;            // K elems per chunk
constexpr int RSB   = 80;            // A smem row stride (64B fp16 + 16B pad)
constexpr int PL_A  = 128 * RSB;     // 10240 B  (128 m-rows)
constexpr int RSB_B = 528;           // B smem row stride (512B fp32 + 16B pad)
constexpr int PL_B  = KC * RSB_B;    // 16896 B  (32 k-rows x 128 n fp32)
constexpr int STG_T = PL_A + PL_B;   // 27136 B per stage
constexpr int SMEM_G = 1024 + 2 * STG_T;   // 55296 B

// ---------------- device-global scratch (256B-aligned: cp.async-safe) ----
__device__ __align__(256) int   g_top_i[2 * T_];
__device__ __align__(256) float g_top_w[2 * T_];
__device__ __align__(256) float g_probs[T_ * E_];
__device__ __align__(256) float g_probsum[E_];
__device__ __align__(256) int   g_cnt[E_];
__device__ __align__(256) int   g_cursor[E_];
__device__ __align__(256) int   g_aoff[E_ + 1];
__device__ __align__(256) int   g_tile_expert[NT];
__device__ __align__(256) int   g_assign_token[RP];
__device__ __align__(256) float g_assign_w[RP];
__device__ __align__(256) int   g_token_slot[2 * T_];

__device__ __align__(256) __half g_x16[T_ * D_];
__device__ __align__(256) __half g_hh[RP * H_];       // h in fp16
__device__ __align__(256) float g_y[(size_t)RP * D_];

// ---------------- PTX helpers (baseline PTX only) ----------------
__device__ __forceinline__ uint32_t smem_u32(const void* p) {
    return (uint32_t)__cvta_generic_to_shared(p);
}
__device__ __forceinline__ void cpa16(uint32_t s, const void* g) {
    asm volatile("cp.async.cg.shared.global [%0], [%1], 16;\n" :: "r"(s), "l"(g));
}
__device__ __forceinline__ void cpa_commit() {
    asm volatile("cp.async.commit_group;\n" ::: "memory");
}
__device__ __forceinline__ void ldm_x4(uint32_t* r, uint32_t a) {
    asm volatile("ldmatrix.sync.aligned.m8n8.x4.shared.b16 {%0,%1,%2,%3}, [%4];"
                 : "=r"(r[0]), "=r"(r[1]), "=r"(r[2]), "=r"(r[3]) : "r"(a));
}
// pack {lo, hi} fp32 -> fp16x2 (first PTX source = HIGH half)
__device__ __forceinline__ uint32_t pack_f16x2(float lo, float hi) {
    uint32_t d;
    asm("cvt.rn.f16x2.f32 %0, %1, %2;" : "=r"(d) : "f"(hi), "f"(lo));
    return d;
}
__device__ __forceinline__ void mma_f16(float* d, const uint32_t* a, const uint32_t* b) {
    asm volatile(
        "mma.sync.aligned.m16n8k16.row.col.f32.f16.f16.f32 "
        "{%0,%1,%2,%3}, {%4,%5,%6,%7}, {%8,%9}, {%0,%1,%2,%3};"
        : "+f"(d[0]), "+f"(d[1]), "+f"(d[2]), "+f"(d[3])
        : "r"(a[0]), "r"(a[1]), "r"(a[2]), "r"(a[3]), "r"(b[0]), "r"(b[1]));
}

// ---------------- reset ----------------
__global__ void k_reset() {
    int i = blockIdx.x * blockDim.x + threadIdx.x;
    if (i < RP) { g_assign_token[i] = -1; g_assign_w[i] = 0.f; }
    if (i < E_) g_cnt[i] = 0;
}

// ---------------- router ----------------
__global__ void k_router(const float* __restrict__ x, const float* __restrict__ Wg) {
    int t = blockIdx.x;
    int lane = threadIdx.x & 31, w = threadIdx.x >> 5;
    const float* xt = x + (size_t)t * D_;
    const float* wg = Wg + (size_t)w * D_;
    float s = 0.f;
    #pragma unroll 8
    for (int j = lane; j < D_; j += 32) s += xt[j] * wg[j];
    #pragma unroll
    for (int o = 16; o; o >>= 1) s += __shfl_xor_sync(0xffffffffu, s, o);
    __shared__ float sl[E_];
    if (lane == 0) sl[w] = s;
    __syncthreads();
    if (threadIdx.x == 0) {
        float mx = sl[0];
        #pragma unroll
        for (int e = 1; e < E_; e++) mx = fmaxf(mx, sl[e]);
        float p[E_], sum = 0.f;
        #pragma unroll
        for (int e = 0; e < E_; e++) { p[e] = __expf(sl[e] - mx); sum += p[e]; }
        float inv = 1.f / sum;
        #pragma unroll
        for (int e = 0; e < E_; e++) { p[e] *= inv; g_probs[t * E_ + e] = p[e]; }
        int i0 = 0;
        #pragma unroll
        for (int e = 1; e < E_; e++) if (p[e] > p[i0]) i0 = e;
        int i1 = -1;
        #pragma unroll
        for (int e = 0; e < E_; e++) {
            if (e == i0) continue;
            if (i1 < 0 || p[e] > p[i1]) i1 = e;
        }
        float v0 = p[i0], v1 = p[i1], s2 = v0 + v1;
        g_top_i[2 * t] = i0;  g_top_i[2 * t + 1] = i1;
        g_top_w[2 * t] = v0 / s2;  g_top_w[2 * t + 1] = v1 / s2;
        atomicAdd(&g_cnt[i0], 1);
        atomicAdd(&g_cnt[i1], 1);
    }
}

__global__ void k_probs_reduce() {
    int e = blockIdx.x, tid = threadIdx.x;
    float s = 0.f;
    for (int t = tid; t < T_; t += 256) s += g_probs[t * E_ + e];
    __shared__ float red[256];
    red[tid] = s; __syncthreads();
    for (int o = 128; o; o >>= 1) { if (tid < o) red[tid] += red[tid + o]; __syncthreads(); }
    if (tid == 0) g_probsum[e] = red[0];
}

__global__ void k_plan() {
    if (threadIdx.x == 0) {
        int off = 0;
        for (int e = 0; e < E_; e++) {
            g_aoff[e] = off;
            int c = g_cnt[e];
            int tiles = (c + TM - 1) / TM;
            int bt = off / TM;
            for (int tt = 0; tt < tiles; tt++) g_tile_expert[bt + tt] = e;
            off += tiles * TM;
            g_cursor[e] = 0;
        }
        g_aoff[E_] = off;
        for (int m = off / TM; m < NT; m++) g_tile_expert[m] = -1;
    }
}

__global__ void k_scatter() {
    int t = blockIdx.x * blockDim.x + threadIdx.x;
    if (t >= T_) return;
    #pragma unroll
    for (int k = 0; k < TOPK; k++) {
        int e = g_top_i[2 * t + k];
        int pos = atomicAdd(&g_cursor[e], 1);
        int slot = g_aoff[e] + pos;
        g_assign_token[slot] = t;
        g_assign_w[slot] = g_top_w[2 * t + k];
        g_token_slot[2 * t + k] = slot;
    }
}

// ---------------- prep: fp32 -> fp16 (x only; weights stream fp32) -------
__global__ void k_cvt_x(const float* __restrict__ x) {
    int i = blockIdx.x * 256 + threadIdx.x;
    if (i < T_ * D_) g_x16[i] = __float2half(x[i]);
}

// ---------------- grouped GEMM via mma.sync ------------------------------
// A: fp16 smem plane + ldmatrix (as R16).  B: fp32 weight tile [KC][128]
// cp.async'd DIRECTLY from W (already [k][n]); fragments built with scalar
// LDS.32 + cvt.rn.f16x2 in-loop (issue slack proven by R16 neutrality).
// Bank checks: A ldmatrix conflict-free (RSB=80); B LDS bank = (8t+4δ+g)%32,
// all 32 distinct (RSB_B=528).
template<bool G1>
__global__ __launch_bounds__(256, 2) void k_gemm_mma(
        const float* __restrict__ W, const float* __restrict__ bias_all) {
    int mt = blockIdx.y, nb = blockIdx.x;
    int e = g_tile_expert[mt];
    if (e < 0) return;
    extern __shared__ char smem[];
    float* s_bias = (float*)smem;
    int*   s_tok  = (int*)(smem + 512);
    char*  sdata  = smem + 1024;
    uint32_t sb32 = smem_u32(smem) + 1024;
    constexpr int KD  = G1 ? D_ : H_;      // contraction extent
    constexpr int NBW = G1 ? H_ : D_;      // output width (= W row stride)
    constexpr int C   = KD / KC;
    int tid = threadIdx.x, lane = tid & 31, wid = tid >> 5;
    int row0 = mt * TM;

    if (tid < 128) s_bias[tid] = bias_all[(size_t)e * NBW + nb * 128 + tid];
    if (G1 && tid < 128) { int tk = g_assign_token[row0 + tid]; s_tok[tid] = tk < 0 ? 0 : tk; }
    __syncthreads();

    const __half* A = G1 ? g_x16 : g_hh;
    size_t wbase = (size_t)e * ((size_t)D_ * H_) + (size_t)(nb * 128);  // + k*NBW

    auto load_chunk = [&](int c, int s) {
        uint32_t st = sb32 + s * STG_T;
        int k0 = c * KC;
        #pragma unroll
        for (int q = tid; q < 512; q += 256) {           // A: 128 rows x 64B fp16
            int r = q >> 2, cc = q & 3;
            size_t go = (G1 ? (size_t)s_tok[r] * D_ : (size_t)(row0 + r) * H_) + k0 + cc * 8;
            cpa16(st + (uint32_t)(r * RSB + cc * 16), A + go);
        }
        #pragma unroll
        for (int q = tid; q < 1024; q += 256) {          // B: 32 k-rows x 512B fp32
            int r = q >> 5, cc = q & 31;
            size_t go = wbase + (size_t)(k0 + r) * NBW + cc * 4;
            cpa16(st + PL_A + (uint32_t)(r * RSB_B + cc * 16), W + go);
        }
        cpa_commit();
    };

    int wm = (wid & 3) * 32, wn = (wid >> 2) * 64;
    int g = lane >> 2, tig = lane & 3;
    // A ldmatrix lane address (R16-proven)
    uint32_t aLM = (uint32_t)((wm + (lane & 7) + ((lane >> 3) & 1) * 8) * RSB
                              + (lane >> 4) * 16);
    // B per-thread fp32 column base (bytes): col n = wn + 8j + g
    uint32_t bCol = (uint32_t)((wn + g) * 4);

    float acc[2][8][4] = {};
    load_chunk(0, 0);
    for (int c = 0; c < C; ++c) {
        int s = c & 1;
        if (c + 1 < C) {
            load_chunk(c + 1, s ^ 1);
            asm volatile("cp.async.wait_group 1;\n" ::: "memory");
        } else {
            asm volatile("cp.async.wait_group 0;\n" ::: "memory");
        }
        __syncthreads();
        uint32_t pA = sb32 + s * STG_T;
        char*    pB = sdata + s * STG_T + PL_A;
        #pragma unroll
        for (int ks = 0; ks < 2; ks++) {
            uint32_t am[8], bx[16];
            ldm_x4(am,     pA + aLM + ks * 32);              // m-tile 0
            ldm_x4(am + 4, pA + aLM + 16 * RSB + ks * 32);   // m-tile 1
            char* pBk = pB + ks * 16 * RSB_B;
            #pragma unroll
            for (int j = 0; j < 8; j++) {                    // n8 blocks
                char* cb = pBk + bCol + j * 32;              // +8 cols fp32
                float f0 = *(const float*)(cb + (2 * tig)     * RSB_B);
                float f1 = *(const float*)(cb + (2 * tig + 1) * RSB_B);
                float f2 = *(const float*)(cb + (8 + 2 * tig) * RSB_B);
                float f3 = *(const float*)(cb + (9 + 2 * tig) * RSB_B);
                bx[2 * j]     = pack_f16x2(f0, f1);
                bx[2 * j + 1] = pack_f16x2(f2, f3);
            }
            #pragma unroll
            for (int m = 0; m < 2; m++)
                #pragma unroll
                for (int n = 0; n < 8; n++)
                    mma_f16(acc[m][n], am + 4 * m, bx + 2 * n);
        }
        __syncthreads();
    }

    // ---- epilogue ----
    int rbase = row0 + wm + g;
    int cloc0 = wn + tig * 2;
    #pragma unroll
    for (int m = 0; m < 2; m++) {
        #pragma unroll
        for (int n = 0; n < 8; n++) {
            int cl = cloc0 + n * 8;
            int gc = nb * 128 + cl;
            float b0 = s_bias[cl], b1 = s_bias[cl + 1];
            #pragma unroll
            for (int hrow = 0; hrow < 2; hrow++) {
                int gr = rbase + m * 16 + hrow * 8;
                float v0 = acc[m][n][2 * hrow + 0] + b0;
                float v1 = acc[m][n][2 * hrow + 1] + b1;
                if (G1) {
                    float s0 = v0 * __fdividef(1.f, 1.f + __expf(-v0));
                    float s1 = v1 * __fdividef(1.f, 1.f + __expf(-v1));
                    __half2 hp; hp.x = __float2half(s0); hp.y = __float2half(s1);
                    *(__half2*)(g_hh + (size_t)gr * H_ + gc) = hp;
                } else {
                    size_t o = (size_t)gr * D_ + gc;
                    float2 fv; fv.x = v0; fv.y = v1;
                    *(float2*)(g_y + o) = fv;
                }
            }
        }
    }
}

// ---------------- combine + aux ----------------
__global__ void k_combine(float* __restrict__ out) {
    int idx = blockIdx.x * 256 + threadIdx.x;
    if (idx >= T_ * D_ / 4) return;
    int t = idx / (D_ / 4);
    int v = idx % (D_ / 4);
    int s0 = g_token_slot[2 * t], s1 = g_token_slot[2 * t + 1];
    float w0 = g_assign_w[s0], w1 = g_assign_w[s1];
    float4 y0 = *(const float4*)(g_y + (size_t)s0 * D_ + v * 4);
    float4 y1 = *(const float4*)(g_y + (size_t)s1 * D_ + v * 4);
    float4 o;
    o.x = w0 * y0.x + w1 * y1.x;
    o.y = w0 * y0.y + w1 * y1.y;
    o.z = w0 * y0.z + w1 * y1.z;
    o.w = w0 * y0.w + w1 * y1.w;
    *(float4*)(out + (size_t)t * D_ + v * 4) = o;
}

__global__ void k_aux(float* __restrict__ out, int out_size) {
    if (threadIdx.x == 0 && out_size > T_ * D_) {
        float a = 0.f;
        #pragma unroll
        for (int e = 0; e < E_; e++)
            a += ((float)g_cnt[e] / (float)T_) * (g_probsum[e] / (float)T_);
        out[(size_t)T_ * D_] = (float)E_ * a;
    }
}

// ---------------- launch ----------------
extern "C" void kernel_launch(void* const* d_in, const int* in_sizes, int n_in,
                              void* d_out, int out_size) {
    const float* x  = (const float*)d_in[0];
    const float* Wg = (const float*)d_in[1];
    const float* W1 = (const float*)d_in[2];
    const float* b1 = (const float*)d_in[3];
    const float* W2 = (const float*)d_in[4];
    const float* b2 = (const float*)d_in[5];
    float* out = (float*)d_out;
    (void)in_sizes; (void)n_in;

    cudaFuncSetAttribute(k_gemm_mma<true>,
                         cudaFuncAttributeMaxDynamicSharedMemorySize, SMEM_G);
    cudaFuncSetAttribute(k_gemm_mma<false>,
                         cudaFuncAttributeMaxDynamicSharedMemorySize, SMEM_G);

    k_reset<<<(RP + 255) / 256, 256>>>();
    k_router<<<T_, 256>>>(x, Wg);
    k_probs_reduce<<<E_, 256>>>();
    k_plan<<<1, 32>>>();
    k_scatter<<<(T_ + 255) / 256, 256>>>();

    k_cvt_x<<<(T_ * D_ + 255) / 256, 256>>>(x);   // only x needs fp16 prep

    k_gemm_mma<true ><<<dim3(H_ / 128, NT), 256, SMEM_G>>>(W1, b1);
    k_gemm_mma<false><<<dim3(D_ / 128, NT), 256, SMEM_G>>>(W2, b2);

    k_combine<<<(T_ * D_ / 4 + 255) / 256, 256>>>(out);
    k_aux<<<1, 32>>>(out, out_size);
}